// round 15
// baseline (speedup 1.0000x reference)
#include <cuda_runtime.h>
#include <cuda_bf16.h>
#include <cstdint>
#include <math.h>

#define BROWS 1024
#define DDIM  8192
#define HDIM  1024
#define GGRP  8
#define SCDIM 2048
#define XDIM  3072
#define KB1   4096
#define NB2   3072
#define YDIM  24576

// ---------------- scratch (__device__ globals; no allocs allowed) ----------
__device__ float g_p1 [4 * BROWS * HDIM];    // branch1 split-K partials
__device__ float g_p2 [2 * BROWS * HDIM];    // branch2 split-K partials
__device__ float g_p3 [BROWS * HDIM];        // branch3 preact (incl. b3)
__device__ float g_ph [BROWS * DDIM];        // grouped1 preact (no bias)
__device__ float g_y  [BROWS * YDIM];

__device__ __nv_bfloat16 g_d16 [BROWS * DDIM];
__device__ __nv_bfloat16 g_s16 [BROWS * SCDIM];
__device__ __nv_bfloat16 g_w1  [HDIM * DDIM];
__device__ __nv_bfloat16 g_w2  [HDIM * SCDIM];
__device__ __nv_bfloat16 g_wb1t[(size_t)GGRP * HDIM * KB1];   // [g][o=1024][i=4096]
__device__ __nv_bfloat16 g_wb2t[(size_t)GGRP * NB2 * HDIM];   // [g][o=3072][i=1024]
__device__ __nv_bfloat16 g_x16 [BROWS * XDIM];
__device__ __nv_bfloat16 g_h16 [BROWS * DDIM];

// ---------------- helpers --------------------------------------------------
__device__ __forceinline__ uint32_t smem_u32(const void* p) {
    uint32_t a;
    asm("{ .reg .u64 t; cvta.to.shared.u64 t, %1; cvt.u32.u64 %0, t; }" : "=r"(a) : "l"(p));
    return a;
}
#define CP16(s, gp) \
    asm volatile("cp.async.cg.shared.global [%0], [%1], 16;" :: "r"(s), "l"(gp))
#define CP_COMMIT() asm volatile("cp.async.commit_group;" ::: "memory")

__device__ __forceinline__ void ldmx4(uint32_t& r0, uint32_t& r1, uint32_t& r2, uint32_t& r3,
                                      uint32_t addr) {
    asm volatile("ldmatrix.sync.aligned.m8n8.x4.shared.b16 {%0,%1,%2,%3}, [%4];"
                 : "=r"(r0), "=r"(r1), "=r"(r2), "=r"(r3) : "r"(addr));
}
__device__ __forceinline__ void mma16816(float* c, const uint32_t* a, const uint32_t* b) {
    asm volatile("mma.sync.aligned.m16n8k16.row.col.f32.bf16.bf16.f32 "
                 "{%0,%1,%2,%3}, {%4,%5,%6,%7}, {%8,%9}, {%0,%1,%2,%3};"
                 : "+f"(c[0]), "+f"(c[1]), "+f"(c[2]), "+f"(c[3])
                 : "r"(a[0]), "r"(a[1]), "r"(a[2]), "r"(a[3]), "r"(b[0]), "r"(b[1]));
}

// ---------------- HMMA GEMM (split-K via partial buffers) ------------------
// z = g * nsplit + sk.  mode 0: C[g-block] = acc + bias.
// mode 2: (C + sk*partStride)[g-block] = acc   (raw partial, no bias)
// Ain = (k < kSplit) ? A0[b*ldA0 + g*gsA0 + k] : A1[b*ldA1 + g*gsA1 + (k-kSplit)]
// Tile: 128x128x32, 256 threads, 8 warps (4M x 2N), 5-stage cp.async pipeline
// (3 stages in flight steady-state), one __syncthreads per k-iter.
#define BKE   32
#define LDS_P 40
#define ASTG  (128 * LDS_P * 2)       // 10240 B per operand per stage
#define NSTG  5
#define SMEM_BYTES (2 * NSTG * ASTG)  // 102400

__global__ __launch_bounds__(256, 2) void gemm_mma(
    const __nv_bfloat16* __restrict__ A0, long ldA0, long gsA0,
    const __nv_bfloat16* __restrict__ A1, long ldA1, long gsA1, int kSplit,
    const __nv_bfloat16* __restrict__ B,  long ldB,  long gsB,
    const float* __restrict__ bias, long gsBias,
    float* __restrict__ C, long ldc, long gsC, long partStride,
    int K, int nsplit, int mode)
{
    extern __shared__ __align__(16) char smem[];
    const uint32_t sb = smem_u32(smem);
    const int t    = threadIdx.x;
    const int lane = t & 31;
    const int wid  = t >> 5;
    const int wm   = wid & 3;
    const int wn   = wid >> 2;
    const int g    = blockIdx.z / nsplit;
    const int sk   = blockIdx.z - g * nsplit;
    const int m0 = blockIdx.x * 128;
    const int n0 = blockIdx.y * 128;

    const int Kc    = K / nsplit;
    const int kBase = sk * Kc;
    const int nkb   = Kc / BKE;         // >= 32 for all our shapes

    const int lrow  = t >> 1;
    const int lhalf = (t & 1) * 16;

    float acc[2][8][4];
#pragma unroll
    for (int i = 0; i < 2; i++)
#pragma unroll
        for (int j = 0; j < 8; j++)
#pragma unroll
            for (int r = 0; r < 4; r++) acc[i][j][r] = 0.f;

    auto load_stage = [&](int buf, int kb) {
        const int k0 = kBase + kb * BKE;
        const __nv_bfloat16* ag;
        if (k0 < kSplit)
            ag = A0 + (size_t)(m0 + lrow) * ldA0 + (size_t)g * gsA0 + k0 + lhalf;
        else
            ag = A1 + (size_t)(m0 + lrow) * ldA1 + (size_t)g * gsA1 + (k0 - kSplit) + lhalf;
        uint32_t ad = sb + buf * ASTG + (uint32_t)(lrow * LDS_P + lhalf) * 2;
        CP16(ad, ag);
        CP16(ad + 16, ag + 8);

        const __nv_bfloat16* bg =
            B + (size_t)g * gsB + (size_t)(n0 + lrow) * ldB + k0 + lhalf;
        uint32_t bd = sb + NSTG * ASTG + buf * ASTG + (uint32_t)(lrow * LDS_P + lhalf) * 2;
        CP16(bd, bg);
        CP16(bd + 16, bg + 8);
        CP_COMMIT();
    };

    load_stage(0, 0);
    load_stage(1, 1);
    load_stage(2, 2);
    load_stage(3, 3);

    int buf = 0;
    for (int kb = 0; kb < nkb; kb++) {
        const int rem = nkb - kb - 1;
        if (rem >= 3) {
            asm volatile("cp.async.wait_group 3;" ::: "memory");
        } else if (rem == 2) {
            asm volatile("cp.async.wait_group 2;" ::: "memory");
        } else if (rem == 1) {
            asm volatile("cp.async.wait_group 1;" ::: "memory");
        } else {
            asm volatile("cp.async.wait_group 0;" ::: "memory");
        }
        __syncthreads();

        if (kb + 4 < nkb) {
            int nb = buf + 4; if (nb >= NSTG) nb -= NSTG;
            load_stage(nb, kb + 4);
        }

        const uint32_t aS = sb + buf * ASTG;
        const uint32_t bS = sb + NSTG * ASTG + buf * ASTG;
#pragma unroll
        for (int ks = 0; ks < 2; ks++) {
            uint32_t a[2][4];
#pragma unroll
            for (int mi = 0; mi < 2; mi++) {
                uint32_t ra = aS + (uint32_t)((wm * 32 + mi * 16 + (lane & 15)) * LDS_P
                                              + ks * 16 + (lane >> 4) * 8) * 2;
                ldmx4(a[mi][0], a[mi][1], a[mi][2], a[mi][3], ra);
            }
            uint32_t b[8][2];
#pragma unroll
            for (int np = 0; np < 4; np++) {
                uint32_t rb = bS + (uint32_t)((wn * 64 + np * 16 + ((lane >> 4) << 3) + (lane & 7)) * LDS_P
                                              + ks * 16 + ((lane >> 3) & 1) * 8) * 2;
                ldmx4(b[2 * np][0], b[2 * np][1], b[2 * np + 1][0], b[2 * np + 1][1], rb);
            }
#pragma unroll
            for (int mi = 0; mi < 2; mi++)
#pragma unroll
                for (int ni = 0; ni < 8; ni++)
                    mma16816(acc[mi][ni], a[mi], b[ni]);
        }
        if (++buf == NSTG) buf = 0;
    }
    __syncthreads();

    // ---- epilogue ----
    if (mode == 0) {
        const float* bg = bias + (size_t)g * gsBias + n0 + wn * 64;
#pragma unroll
        for (int mi = 0; mi < 2; mi++) {
            const int r0 = m0 + wm * 32 + mi * 16 + (lane >> 2);
            float* c0 = C + (size_t)r0 * ldc + (size_t)g * gsC + n0 + wn * 64;
            float* c1 = c0 + 8 * ldc;
#pragma unroll
            for (int ni = 0; ni < 8; ni++) {
                const int col = ni * 8 + (lane & 3) * 2;
                const float bx = bg[col], by = bg[col + 1];
                *(float2*)(c0 + col) = make_float2(acc[mi][ni][0] + bx, acc[mi][ni][1] + by);
                *(float2*)(c1 + col) = make_float2(acc[mi][ni][2] + bx, acc[mi][ni][3] + by);
            }
        }
    } else {
        float* Cp = C + (size_t)sk * partStride;
#pragma unroll
        for (int mi = 0; mi < 2; mi++) {
            const int r0 = m0 + wm * 32 + mi * 16 + (lane >> 2);
            float* c0 = Cp + (size_t)r0 * ldc + (size_t)g * gsC + n0 + wn * 64;
            float* c1 = c0 + 8 * ldc;
#pragma unroll
            for (int ni = 0; ni < 8; ni++) {
                const int col = ni * 8 + (lane & 3) * 2;
                *(float2*)(c0 + col) = make_float2(acc[mi][ni][0], acc[mi][ni][1]);
                *(float2*)(c1 + col) = make_float2(acc[mi][ni][2], acc[mi][ni][3]);
            }
        }
    }
}

// ---------------- conversion / transpose ----------------------------------
__global__ __launch_bounds__(256) void f32_to_bf16_kernel(
    const float* __restrict__ in, __nv_bfloat16* __restrict__ out, int n4)
{
    int i = blockIdx.x * blockDim.x + threadIdx.x;
    if (i >= n4) return;
    float4 v = ((const float4*)in)[i];
    ushort4 u;
    u.x = __bfloat16_as_ushort(__float2bfloat16(v.x));
    u.y = __bfloat16_as_ushort(__float2bfloat16(v.y));
    u.z = __bfloat16_as_ushort(__float2bfloat16(v.z));
    u.w = __bfloat16_as_ushort(__float2bfloat16(v.w));
    ((ushort4*)out)[i] = u;
}

// in[g][r][c] (fp32) -> out[g][c][r] (bf16). 64x64 tiles.
__global__ __launch_bounds__(256) void transpose_to_bf16(
    const float* __restrict__ in, __nv_bfloat16* __restrict__ out, int R, int Cc)
{
    __shared__ float tile[64][65];   // [c][r]
    const int g = blockIdx.z;
    const float* ing = in + (size_t)g * R * Cc;
    __nv_bfloat16* og = out + (size_t)g * R * Cc;
    const int c0 = blockIdx.x * 64, r0 = blockIdx.y * 64;
    const int tx = threadIdx.x & 15;
    const int ty = threadIdx.x >> 4;

#pragma unroll
    for (int q = 0; q < 4; q++) {
        const int r = ty + q * 16;
        float4 v = *(const float4*)(ing + (size_t)(r0 + r) * Cc + c0 + tx * 4);
        tile[tx * 4 + 0][r] = v.x;
        tile[tx * 4 + 1][r] = v.y;
        tile[tx * 4 + 2][r] = v.z;
        tile[tx * 4 + 3][r] = v.w;
    }
    __syncthreads();
#pragma unroll
    for (int q = 0; q < 4; q++) {
        const int c = ty + q * 16;
        ushort4 u;
        u.x = __bfloat16_as_ushort(__float2bfloat16(tile[c][tx * 4 + 0]));
        u.y = __bfloat16_as_ushort(__float2bfloat16(tile[c][tx * 4 + 1]));
        u.z = __bfloat16_as_ushort(__float2bfloat16(tile[c][tx * 4 + 2]));
        u.w = __bfloat16_as_ushort(__float2bfloat16(tile[c][tx * 4 + 3]));
        *(ushort4*)(og + (size_t)(c0 + c) * R + r0 + tx * 4) = u;
    }
}

// ---------------- fused kernels --------------------------------------------
__global__ __launch_bounds__(256) void branch3_init_kernel(
    const float* __restrict__ action,
    const float* __restrict__ W3,
    const float* __restrict__ b3)
{
    const int b = blockIdx.x;
    float a0 = action[b * 2 + 0];
    float a1 = action[b * 2 + 1];
    a0 = a0 / fmaxf(1.f, fabsf(a0));
    a1 = a1 / fmaxf(1.f, fabsf(a1));
    for (int h = threadIdx.x; h < HDIM; h += blockDim.x) {
        g_p3[(size_t)b * HDIM + h] =
            fmaf(a0, W3[h * 2 + 0], fmaf(a1, W3[h * 2 + 1], b3[h]));
    }
}

// Sum nparts split-K partials + bias, rmsnorm+silu -> bf16.
template<int ITERS>
__global__ __launch_bounds__(256) void rmsnorm_multi(
    const float* __restrict__ src, long partStride, int nparts,
    const float* __restrict__ bias, const float* __restrict__ scale,
    __nv_bfloat16* __restrict__ dst, int lddst, int odst)
{
    const int L = ITERS * 1024;
    const int b = blockIdx.x;
    const int tid = threadIdx.x;
    const float* row = src + (size_t)b * L;

    float v[ITERS][4];
    float ss = 0.f;
#pragma unroll
    for (int q = 0; q < ITERS; q++) {
        const int col = (tid + q * 256) * 4;
        float4 x = *(const float4*)(row + col);
        for (int p = 1; p < nparts; p++) {
            float4 y = *(const float4*)(row + (size_t)p * partStride + col);
            x.x += y.x; x.y += y.y; x.z += y.z; x.w += y.w;
        }
        if (bias) {
            float4 bv = *(const float4*)(bias + col);
            x.x += bv.x; x.y += bv.y; x.z += bv.z; x.w += bv.w;
        }
        v[q][0] = x.x; v[q][1] = x.y; v[q][2] = x.z; v[q][3] = x.w;
        ss += x.x * x.x + x.y * x.y + x.z * x.z + x.w * x.w;
    }

    __shared__ float red[256];
    red[tid] = ss;
    __syncthreads();
#pragma unroll
    for (int s = 128; s > 0; s >>= 1) {
        if (tid < s) red[tid] += red[tid + s];
        __syncthreads();
    }
    const float rms = rsqrtf(red[0] / (float)L + 1e-6f);

    __nv_bfloat16* drow = dst + (size_t)b * lddst + odst;
#pragma unroll
    for (int q = 0; q < ITERS; q++) {
        const int col = (tid + q * 256) * 4;
        float4 sc = *(const float4*)(scale + col);
        float t0 = v[q][0] * rms * sc.x;
        float t1 = v[q][1] * rms * sc.y;
        float t2 = v[q][2] * rms * sc.z;
        float t3 = v[q][3] * rms * sc.w;
        ushort4 o;
        o.x = __bfloat16_as_ushort(__float2bfloat16(t0 / (1.f + expf(-t0))));
        o.y = __bfloat16_as_ushort(__float2bfloat16(t1 / (1.f + expf(-t1))));
        o.z = __bfloat16_as_ushort(__float2bfloat16(t2 / (1.f + expf(-t2))));
        o.w = __bfloat16_as_ushort(__float2bfloat16(t3 / (1.f + expf(-t3))));
        *(ushort4*)(drow + col) = o;
    }
}

__global__ __launch_bounds__(256) void gate_kernel(
    const float* __restrict__ deter, float* __restrict__ out)
{
    const int idx = blockIdx.x * blockDim.x + threadIdx.x;
    const int b  = idx >> 13;
    const int gd = idx & 8191;
    const int g  = gd >> 10;
    const int m  = gd & 1023;
    const float* yb = g_y + (size_t)b * YDIM + g * NB2;
    const float r = yb[m];
    const float c = yb[1024 + m];
    const float u = yb[2048 + m];
    const float reset  = 1.f / (1.f + expf(-r));
    const float cand   = tanhf(reset * c);
    const float update = 1.f / (1.f + expf(-(u - 1.f)));
    out[idx] = update * cand + (1.f - update) * deter[idx];
}

// ---------------------------------------------------------------------------
extern "C" void kernel_launch(void* const* d_in, const int* in_sizes, int n_in,
                              void* d_out, int out_size)
{
    const float* deter  = (const float*)d_in[0];
    const float* stoch  = (const float*)d_in[1];
    const float* action = (const float*)d_in[2];
    const float* W1  = (const float*)d_in[3];
    const float* b1  = (const float*)d_in[4];
    const float* s1  = (const float*)d_in[5];
    const float* W2  = (const float*)d_in[6];
    const float* b2  = (const float*)d_in[7];
    const float* s2  = (const float*)d_in[8];
    const float* W3  = (const float*)d_in[9];
    const float* b3  = (const float*)d_in[10];
    const float* s3  = (const float*)d_in[11];
    const float* Wb1 = (const float*)d_in[12];
    const float* bb1 = (const float*)d_in[13];
    const float* sb1 = (const float*)d_in[14];
    const float* Wb2 = (const float*)d_in[15];
    const float* bb2 = (const float*)d_in[16];
    float* out = (float*)d_out;

    float *p1, *p2, *p3, *ph, *yp;
    __nv_bfloat16 *d16, *s16p, *w1p, *w2p, *wb1t, *wb2t, *x16, *h16;
    cudaGetSymbolAddress((void**)&p1,   g_p1);
    cudaGetSymbolAddress((void**)&p2,   g_p2);
    cudaGetSymbolAddress((void**)&p3,   g_p3);
    cudaGetSymbolAddress((void**)&ph,   g_ph);
    cudaGetSymbolAddress((void**)&yp,   g_y);
    cudaGetSymbolAddress((void**)&d16,  g_d16);
    cudaGetSymbolAddress((void**)&s16p, g_s16);
    cudaGetSymbolAddress((void**)&w1p,  g_w1);
    cudaGetSymbolAddress((void**)&w2p,  g_w2);
    cudaGetSymbolAddress((void**)&wb1t, g_wb1t);
    cudaGetSymbolAddress((void**)&wb2t, g_wb2t);
    cudaGetSymbolAddress((void**)&x16,  g_x16);
    cudaGetSymbolAddress((void**)&h16,  g_h16);

    cudaFuncSetAttribute(gemm_mma, cudaFuncAttributeMaxDynamicSharedMemorySize, SMEM_BYTES);

    static cudaStream_t s_aux = nullptr;
    static cudaEvent_t ev_fork = nullptr, ev_join = nullptr;
    if (!s_aux) {
        cudaStreamCreateWithFlags(&s_aux, cudaStreamNonBlocking);
        cudaEventCreateWithFlags(&ev_fork, cudaEventDisableTiming);
        cudaEventCreateWithFlags(&ev_join, cudaEventDisableTiming);
    }

    // ---- main stream: conversions ordered so GEMM1 is the 6th launch ----
    f32_to_bf16_kernel<<<(BROWS * SCDIM / 4 + 255) / 256, 256>>>(stoch, s16p, BROWS * SCDIM / 4);
    f32_to_bf16_kernel<<<(HDIM * SCDIM / 4 + 255) / 256, 256>>>(W2, w2p, HDIM * SCDIM / 4);
    f32_to_bf16_kernel<<<(BROWS * DDIM / 4 + 255) / 256, 256>>>(deter, d16, BROWS * DDIM / 4);
    f32_to_bf16_kernel<<<(HDIM * DDIM / 4 + 255) / 256, 256>>>(W1, w1p, HDIM * DDIM / 4);
    branch3_init_kernel<<<BROWS, 256>>>(action, W3, b3);

    // branch1: K=8192 split 4 -> g_p1 partials   (launch #6 for ncu)
    gemm_mma<<<dim3(8, 8, 4), 256, SMEM_BYTES>>>(
        d16, DDIM, 0,  d16, DDIM, 0, DDIM,
        w1p, DDIM, 0,  nullptr, 0,
        p1, HDIM, 0, (long)BROWS * HDIM, DDIM, 4, 2);

    // ---- fork: weight transposes on aux stream (join before grouped1) ----
    cudaEventRecord(ev_fork, (cudaStream_t)0);
    cudaStreamWaitEvent(s_aux, ev_fork, 0);
    transpose_to_bf16<<<dim3(1024 / 64, 4096 / 64, GGRP), 256, 0, s_aux>>>(Wb1, wb1t, 4096, 1024);
    transpose_to_bf16<<<dim3(3072 / 64, 1024 / 64, GGRP), 256, 0, s_aux>>>(Wb2, wb2t, 1024, 3072);
    cudaEventRecord(ev_join, s_aux);

    // branch2: K=2048 split 2 -> g_p2 partials
    gemm_mma<<<dim3(8, 8, 2), 256, SMEM_BYTES>>>(
        s16p, SCDIM, 0, s16p, SCDIM, 0, SCDIM,
        w2p, SCDIM, 0,  nullptr, 0,
        p2, HDIM, 0, (long)BROWS * HDIM, SCDIM, 2, 2);

    // partial-sum + bias + rmsnorm + SiLU -> bf16 x
    rmsnorm_multi<1><<<BROWS, 256>>>(p1, (long)BROWS * HDIM, 4, b1, s1, x16, XDIM, 0);
    rmsnorm_multi<1><<<BROWS, 256>>>(p2, (long)BROWS * HDIM, 2, b2, s2, x16, XDIM, 1024);
    rmsnorm_multi<1><<<BROWS, 256>>>(p3, 0, 1, nullptr, s3, x16, XDIM, 2048);

    // ---- join: transposes must be done before grouped GEMMs ----
    cudaStreamWaitEvent((cudaStream_t)0, ev_join, 0);

    // Grouped GEMM 1 (no split, raw store): [x | d_g] @ Wb1t[g] -> g_ph
    gemm_mma<<<dim3(8, 8, GGRP), 256, SMEM_BYTES>>>(
        x16, XDIM, 0,
        d16, DDIM, 1024, XDIM,
        wb1t, KB1, (long)HDIM * KB1,
        nullptr, 0,
        ph, DDIM, HDIM, 0, KB1, 1, 2);

    rmsnorm_multi<8><<<BROWS, 256>>>(ph, 0, 1, bb1, sb1, h16, DDIM, 0);

    // Grouped GEMM 2 (store + bias): h_g @ Wb2t[g] -> g_y
    gemm_mma<<<dim3(8, 24, GGRP), 256, SMEM_BYTES>>>(
        h16, DDIM, 1024,
        h16, DDIM, 1024, HDIM,
        wb2t, HDIM, (long)NB2 * HDIM,
        bb2, NB2,
        yp, YDIM, NB2, 0, HDIM, 1, 0);

    gate_kernel<<<(BROWS * DDIM) / 256, 256>>>(deter, out);
}

// round 17
// speedup vs baseline: 1.0694x; 1.0694x over previous
#include <cuda_runtime.h>
#include <cuda_bf16.h>
#include <cstdint>
#include <math.h>

#define BROWS 1024
#define DDIM  8192
#define HDIM  1024
#define GGRP  8
#define SCDIM 2048
#define XDIM  3072
#define KB1   4096
#define NB2   3072
#define YDIM  24576

// ---------------- scratch (__device__ globals; no allocs allowed) ----------
__device__ float g_p1 [4 * BROWS * HDIM];    // branch1 split-K partials
__device__ float g_p2 [2 * BROWS * HDIM];    // branch2 split-K partials
__device__ float g_p3 [BROWS * HDIM];        // branch3 preact (incl. b3)
__device__ float g_ph [2 * BROWS * DDIM];    // grouped1 split-K partials
__device__ float g_y  [BROWS * YDIM];

__device__ __nv_bfloat16 g_d16 [BROWS * DDIM];
__device__ __nv_bfloat16 g_s16 [BROWS * SCDIM];
__device__ __nv_bfloat16 g_w1  [HDIM * DDIM];
__device__ __nv_bfloat16 g_w2  [HDIM * SCDIM];
__device__ __nv_bfloat16 g_wb1t[(size_t)GGRP * HDIM * KB1];   // [g][o=1024][i=4096]
__device__ __nv_bfloat16 g_wb2t[(size_t)GGRP * NB2 * HDIM];   // [g][o=3072][i=1024]
__device__ __nv_bfloat16 g_x16 [BROWS * XDIM];
__device__ __nv_bfloat16 g_h16 [BROWS * DDIM];

// ---------------- helpers --------------------------------------------------
__device__ __forceinline__ uint32_t smem_u32(const void* p) {
    uint32_t a;
    asm("{ .reg .u64 t; cvta.to.shared.u64 t, %1; cvt.u32.u64 %0, t; }" : "=r"(a) : "l"(p));
    return a;
}
#define CP16(s, gp) \
    asm volatile("cp.async.cg.shared.global [%0], [%1], 16;" :: "r"(s), "l"(gp))
#define CP_COMMIT() asm volatile("cp.async.commit_group;" ::: "memory")

__device__ __forceinline__ void ldmx4(uint32_t& r0, uint32_t& r1, uint32_t& r2, uint32_t& r3,
                                      uint32_t addr) {
    asm volatile("ldmatrix.sync.aligned.m8n8.x4.shared.b16 {%0,%1,%2,%3}, [%4];"
                 : "=r"(r0), "=r"(r1), "=r"(r2), "=r"(r3) : "r"(addr));
}
__device__ __forceinline__ void mma16816(float* c, const uint32_t* a, const uint32_t* b) {
    asm volatile("mma.sync.aligned.m16n8k16.row.col.f32.bf16.bf16.f32 "
                 "{%0,%1,%2,%3}, {%4,%5,%6,%7}, {%8,%9}, {%0,%1,%2,%3};"
                 : "+f"(c[0]), "+f"(c[1]), "+f"(c[2]), "+f"(c[3])
                 : "r"(a[0]), "r"(a[1]), "r"(a[2]), "r"(a[3]), "r"(b[0]), "r"(b[1]));
}

// ---------------- HMMA GEMM (R14 frozen config) ----------------------------
// z = g * nsplit + sk.  mode 0: C[g-block] = acc + bias.
// mode 2: (C + sk*partStride)[g-block] = acc   (raw partial, no bias)
// Ain = (k < kSplit) ? A0[b*ldA0 + g*gsA0 + k] : A1[b*ldA1 + g*gsA1 + (k-kSplit)]
// Tile: 128x128x32, 256 threads, 8 warps (4M x 2N), 4-stage cp.async pipeline
// (3 stages in flight steady-state), one __syncthreads per k-iter.
#define BKE   32
#define LDS_P 40
#define ASTG  (128 * LDS_P * 2)       // 10240 B per operand per stage
#define NSTG  4
#define SMEM_BYTES (2 * NSTG * ASTG)  // 81920

__global__ __launch_bounds__(256, 2) void gemm_mma(
    const __nv_bfloat16* __restrict__ A0, long ldA0, long gsA0,
    const __nv_bfloat16* __restrict__ A1, long ldA1, long gsA1, int kSplit,
    const __nv_bfloat16* __restrict__ B,  long ldB,  long gsB,
    const float* __restrict__ bias, long gsBias,
    float* __restrict__ C, long ldc, long gsC, long partStride,
    int K, int nsplit, int mode)
{
    extern __shared__ __align__(16) char smem[];
    const uint32_t sb = smem_u32(smem);
    const int t    = threadIdx.x;
    const int lane = t & 31;
    const int wid  = t >> 5;
    const int wm   = wid & 3;
    const int wn   = wid >> 2;
    const int g    = blockIdx.z / nsplit;
    const int sk   = blockIdx.z - g * nsplit;
    const int m0 = blockIdx.x * 128;
    const int n0 = blockIdx.y * 128;

    const int Kc    = K / nsplit;
    const int kBase = sk * Kc;
    const int nkb   = Kc / BKE;

    const int lrow  = t >> 1;
    const int lhalf = (t & 1) * 16;

    float acc[2][8][4];
#pragma unroll
    for (int i = 0; i < 2; i++)
#pragma unroll
        for (int j = 0; j < 8; j++)
#pragma unroll
            for (int r = 0; r < 4; r++) acc[i][j][r] = 0.f;

    auto load_stage = [&](int buf, int kb) {
        const int k0 = kBase + kb * BKE;
        const __nv_bfloat16* ag;
        if (k0 < kSplit)
            ag = A0 + (size_t)(m0 + lrow) * ldA0 + (size_t)g * gsA0 + k0 + lhalf;
        else
            ag = A1 + (size_t)(m0 + lrow) * ldA1 + (size_t)g * gsA1 + (k0 - kSplit) + lhalf;
        uint32_t ad = sb + buf * ASTG + (uint32_t)(lrow * LDS_P + lhalf) * 2;
        CP16(ad, ag);
        CP16(ad + 16, ag + 8);

        const __nv_bfloat16* bg =
            B + (size_t)g * gsB + (size_t)(n0 + lrow) * ldB + k0 + lhalf;
        uint32_t bd = sb + NSTG * ASTG + buf * ASTG + (uint32_t)(lrow * LDS_P + lhalf) * 2;
        CP16(bd, bg);
        CP16(bd + 16, bg + 8);
        CP_COMMIT();
    };

    load_stage(0, 0);
    load_stage(1, 1);
    load_stage(2, 2);

    for (int kb = 0; kb < nkb; kb++) {
        const int rem = nkb - kb - 1;
        if (rem >= 2) {
            asm volatile("cp.async.wait_group 2;" ::: "memory");
        } else if (rem == 1) {
            asm volatile("cp.async.wait_group 1;" ::: "memory");
        } else {
            asm volatile("cp.async.wait_group 0;" ::: "memory");
        }
        __syncthreads();

        if (kb + 3 < nkb) load_stage((kb + 3) & 3, kb + 3);

        const int buf = kb & 3;
        const uint32_t aS = sb + buf * ASTG;
        const uint32_t bS = sb + NSTG * ASTG + buf * ASTG;
#pragma unroll
        for (int ks = 0; ks < 2; ks++) {
            uint32_t a[2][4];
#pragma unroll
            for (int mi = 0; mi < 2; mi++) {
                uint32_t ra = aS + (uint32_t)((wm * 32 + mi * 16 + (lane & 15)) * LDS_P
                                              + ks * 16 + (lane >> 4) * 8) * 2;
                ldmx4(a[mi][0], a[mi][1], a[mi][2], a[mi][3], ra);
            }
            uint32_t b[8][2];
#pragma unroll
            for (int np = 0; np < 4; np++) {
                uint32_t rb = bS + (uint32_t)((wn * 64 + np * 16 + ((lane >> 4) << 3) + (lane & 7)) * LDS_P
                                              + ks * 16 + ((lane >> 3) & 1) * 8) * 2;
                ldmx4(b[2 * np][0], b[2 * np][1], b[2 * np + 1][0], b[2 * np + 1][1], rb);
            }
#pragma unroll
            for (int mi = 0; mi < 2; mi++)
#pragma unroll
                for (int ni = 0; ni < 8; ni++)
                    mma16816(acc[mi][ni], a[mi], b[ni]);
        }
    }
    __syncthreads();

    // ---- epilogue ----
    if (mode == 0) {
        const float* bg = bias + (size_t)g * gsBias + n0 + wn * 64;
#pragma unroll
        for (int mi = 0; mi < 2; mi++) {
            const int r0 = m0 + wm * 32 + mi * 16 + (lane >> 2);
            float* c0 = C + (size_t)r0 * ldc + (size_t)g * gsC + n0 + wn * 64;
            float* c1 = c0 + 8 * ldc;
#pragma unroll
            for (int ni = 0; ni < 8; ni++) {
                const int col = ni * 8 + (lane & 3) * 2;
                const float bx = bg[col], by = bg[col + 1];
                *(float2*)(c0 + col) = make_float2(acc[mi][ni][0] + bx, acc[mi][ni][1] + by);
                *(float2*)(c1 + col) = make_float2(acc[mi][ni][2] + bx, acc[mi][ni][3] + by);
            }
        }
    } else {
        float* Cp = C + (size_t)sk * partStride;
#pragma unroll
        for (int mi = 0; mi < 2; mi++) {
            const int r0 = m0 + wm * 32 + mi * 16 + (lane >> 2);
            float* c0 = Cp + (size_t)r0 * ldc + (size_t)g * gsC + n0 + wn * 64;
            float* c1 = c0 + 8 * ldc;
#pragma unroll
            for (int ni = 0; ni < 8; ni++) {
                const int col = ni * 8 + (lane & 3) * 2;
                *(float2*)(c0 + col) = make_float2(acc[mi][ni][0], acc[mi][ni][1]);
                *(float2*)(c1 + col) = make_float2(acc[mi][ni][2], acc[mi][ni][3]);
            }
        }
    }
}

// ---------------- conversion / transpose ----------------------------------
__global__ __launch_bounds__(256) void f32_to_bf16_kernel(
    const float* __restrict__ in, __nv_bfloat16* __restrict__ out, int n4)
{
    int i = blockIdx.x * blockDim.x + threadIdx.x;
    if (i >= n4) return;
    float4 v = ((const float4*)in)[i];
    ushort4 u;
    u.x = __bfloat16_as_ushort(__float2bfloat16(v.x));
    u.y = __bfloat16_as_ushort(__float2bfloat16(v.y));
    u.z = __bfloat16_as_ushort(__float2bfloat16(v.z));
    u.w = __bfloat16_as_ushort(__float2bfloat16(v.w));
    ((ushort4*)out)[i] = u;
}

// in[g][r][c] (fp32) -> out[g][c][r] (bf16). 64x64 tiles.
__global__ __launch_bounds__(256) void transpose_to_bf16(
    const float* __restrict__ in, __nv_bfloat16* __restrict__ out, int R, int Cc)
{
    __shared__ float tile[64][65];   // [c][r]
    const int g = blockIdx.z;
    const float* ing = in + (size_t)g * R * Cc;
    __nv_bfloat16* og = out + (size_t)g * R * Cc;
    const int c0 = blockIdx.x * 64, r0 = blockIdx.y * 64;
    const int tx = threadIdx.x & 15;
    const int ty = threadIdx.x >> 4;

#pragma unroll
    for (int q = 0; q < 4; q++) {
        const int r = ty + q * 16;
        float4 v = *(const float4*)(ing + (size_t)(r0 + r) * Cc + c0 + tx * 4);
        tile[tx * 4 + 0][r] = v.x;
        tile[tx * 4 + 1][r] = v.y;
        tile[tx * 4 + 2][r] = v.z;
        tile[tx * 4 + 3][r] = v.w;
    }
    __syncthreads();
#pragma unroll
    for (int q = 0; q < 4; q++) {
        const int c = ty + q * 16;
        ushort4 u;
        u.x = __bfloat16_as_ushort(__float2bfloat16(tile[c][tx * 4 + 0]));
        u.y = __bfloat16_as_ushort(__float2bfloat16(tile[c][tx * 4 + 1]));
        u.z = __bfloat16_as_ushort(__float2bfloat16(tile[c][tx * 4 + 2]));
        u.w = __bfloat16_as_ushort(__float2bfloat16(tile[c][tx * 4 + 3]));
        *(ushort4*)(og + (size_t)(c0 + c) * R + r0 + tx * 4) = u;
    }
}

// ---------------- fused kernels --------------------------------------------
__global__ __launch_bounds__(256) void branch3_init_kernel(
    const float* __restrict__ action,
    const float* __restrict__ W3,
    const float* __restrict__ b3)
{
    const int b = blockIdx.x;
    float a0 = action[b * 2 + 0];
    float a1 = action[b * 2 + 1];
    a0 = a0 / fmaxf(1.f, fabsf(a0));
    a1 = a1 / fmaxf(1.f, fabsf(a1));
    for (int h = threadIdx.x; h < HDIM; h += blockDim.x) {
        g_p3[(size_t)b * HDIM + h] =
            fmaf(a0, W3[h * 2 + 0], fmaf(a1, W3[h * 2 + 1], b3[h]));
    }
}

// Sum nparts split-K partials + bias, rmsnorm+silu -> bf16.
template<int ITERS>
__global__ __launch_bounds__(256) void rmsnorm_multi(
    const float* __restrict__ src, long partStride, int nparts,
    const float* __restrict__ bias, const float* __restrict__ scale,
    __nv_bfloat16* __restrict__ dst, int lddst, int odst)
{
    const int L = ITERS * 1024;
    const int b = blockIdx.x;
    const int tid = threadIdx.x;
    const float* row = src + (size_t)b * L;

    float v[ITERS][4];
    float ss = 0.f;
#pragma unroll
    for (int q = 0; q < ITERS; q++) {
        const int col = (tid + q * 256) * 4;
        float4 x = *(const float4*)(row + col);
        for (int p = 1; p < nparts; p++) {
            float4 y = *(const float4*)(row + (size_t)p * partStride + col);
            x.x += y.x; x.y += y.y; x.z += y.z; x.w += y.w;
        }
        if (bias) {
            float4 bv = *(const float4*)(bias + col);
            x.x += bv.x; x.y += bv.y; x.z += bv.z; x.w += bv.w;
        }
        v[q][0] = x.x; v[q][1] = x.y; v[q][2] = x.z; v[q][3] = x.w;
        ss += x.x * x.x + x.y * x.y + x.z * x.z + x.w * x.w;
    }

    __shared__ float red[256];
    red[tid] = ss;
    __syncthreads();
#pragma unroll
    for (int s = 128; s > 0; s >>= 1) {
        if (tid < s) red[tid] += red[tid + s];
        __syncthreads();
    }
    const float rms = rsqrtf(red[0] / (float)L + 1e-6f);

    __nv_bfloat16* drow = dst + (size_t)b * lddst + odst;
#pragma unroll
    for (int q = 0; q < ITERS; q++) {
        const int col = (tid + q * 256) * 4;
        float4 sc = *(const float4*)(scale + col);
        float t0 = v[q][0] * rms * sc.x;
        float t1 = v[q][1] * rms * sc.y;
        float t2 = v[q][2] * rms * sc.z;
        float t3 = v[q][3] * rms * sc.w;
        ushort4 o;
        o.x = __bfloat16_as_ushort(__float2bfloat16(t0 / (1.f + expf(-t0))));
        o.y = __bfloat16_as_ushort(__float2bfloat16(t1 / (1.f + expf(-t1))));
        o.z = __bfloat16_as_ushort(__float2bfloat16(t2 / (1.f + expf(-t2))));
        o.w = __bfloat16_as_ushort(__float2bfloat16(t3 / (1.f + expf(-t3))));
        *(ushort4*)(drow + col) = o;
    }
}

__global__ __launch_bounds__(256) void gate_kernel(
    const float* __restrict__ deter, float* __restrict__ out)
{
    const int idx = blockIdx.x * blockDim.x + threadIdx.x;
    const int b  = idx >> 13;
    const int gd = idx & 8191;
    const int g  = gd >> 10;
    const int m  = gd & 1023;
    const float* yb = g_y + (size_t)b * YDIM + g * NB2;
    const float r = yb[m];
    const float c = yb[1024 + m];
    const float u = yb[2048 + m];
    const float reset  = 1.f / (1.f + expf(-r));
    const float cand   = tanhf(reset * c);
    const float update = 1.f / (1.f + expf(-(u - 1.f)));
    out[idx] = update * cand + (1.f - update) * deter[idx];
}

// ---------------------------------------------------------------------------
extern "C" void kernel_launch(void* const* d_in, const int* in_sizes, int n_in,
                              void* d_out, int out_size)
{
    const float* deter  = (const float*)d_in[0];
    const float* stoch  = (const float*)d_in[1];
    const float* action = (const float*)d_in[2];
    const float* W1  = (const float*)d_in[3];
    const float* b1  = (const float*)d_in[4];
    const float* s1  = (const float*)d_in[5];
    const float* W2  = (const float*)d_in[6];
    const float* b2  = (const float*)d_in[7];
    const float* s2  = (const float*)d_in[8];
    const float* W3  = (const float*)d_in[9];
    const float* b3  = (const float*)d_in[10];
    const float* s3  = (const float*)d_in[11];
    const float* Wb1 = (const float*)d_in[12];
    const float* bb1 = (const float*)d_in[13];
    const float* sb1 = (const float*)d_in[14];
    const float* Wb2 = (const float*)d_in[15];
    const float* bb2 = (const float*)d_in[16];
    float* out = (float*)d_out;

    float *p1, *p2, *p3, *ph, *yp;
    __nv_bfloat16 *d16, *s16p, *w1p, *w2p, *wb1t, *wb2t, *x16, *h16;
    cudaGetSymbolAddress((void**)&p1,   g_p1);
    cudaGetSymbolAddress((void**)&p2,   g_p2);
    cudaGetSymbolAddress((void**)&p3,   g_p3);
    cudaGetSymbolAddress((void**)&ph,   g_ph);
    cudaGetSymbolAddress((void**)&yp,   g_y);
    cudaGetSymbolAddress((void**)&d16,  g_d16);
    cudaGetSymbolAddress((void**)&s16p, g_s16);
    cudaGetSymbolAddress((void**)&w1p,  g_w1);
    cudaGetSymbolAddress((void**)&w2p,  g_w2);
    cudaGetSymbolAddress((void**)&wb1t, g_wb1t);
    cudaGetSymbolAddress((void**)&wb2t, g_wb2t);
    cudaGetSymbolAddress((void**)&x16,  g_x16);
    cudaGetSymbolAddress((void**)&h16,  g_h16);

    cudaFuncSetAttribute(gemm_mma, cudaFuncAttributeMaxDynamicSharedMemorySize, SMEM_BYTES);

    static cudaStream_t s_aux = nullptr;
    static cudaEvent_t ev_start = nullptr, ev_sW2 = nullptr, ev_b2 = nullptr, ev_join = nullptr;
    if (!s_aux) {
        cudaStreamCreateWithFlags(&s_aux, cudaStreamNonBlocking);
        cudaEventCreateWithFlags(&ev_start, cudaEventDisableTiming);
        cudaEventCreateWithFlags(&ev_sW2, cudaEventDisableTiming);
        cudaEventCreateWithFlags(&ev_b2, cudaEventDisableTiming);
        cudaEventCreateWithFlags(&ev_join, cudaEventDisableTiming);
    }

    // ---- fork point at capture start ----
    cudaEventRecord(ev_start, (cudaStream_t)0);

    // ---- main stream: branch2-independent conversions first ----
    f32_to_bf16_kernel<<<(BROWS * SCDIM / 4 + 255) / 256, 256>>>(stoch, s16p, BROWS * SCDIM / 4);
    f32_to_bf16_kernel<<<(HDIM * SCDIM / 4 + 255) / 256, 256>>>(W2, w2p, HDIM * SCDIM / 4);
    cudaEventRecord(ev_sW2, (cudaStream_t)0);

    f32_to_bf16_kernel<<<(BROWS * DDIM / 4 + 255) / 256, 256>>>(deter, d16, BROWS * DDIM / 4);
    f32_to_bf16_kernel<<<(HDIM * DDIM / 4 + 255) / 256, 256>>>(W1, w1p, HDIM * DDIM / 4);

    // branch1: K=8192 split 4 -> g_p1 partials  (critical path)
    gemm_mma<<<dim3(8, 8, 4), 256, SMEM_BYTES>>>(
        d16, DDIM, 0,  d16, DDIM, 0, DDIM,
        w1p, DDIM, 0,  nullptr, 0,
        p1, HDIM, 0, (long)BROWS * HDIM, DDIM, 4, 2);

    // ---- aux stream: branch3 preact, branch2 GEMM, weight transposes ----
    cudaStreamWaitEvent(s_aux, ev_start, 0);
    branch3_init_kernel<<<BROWS, 256, 0, s_aux>>>(action, W3, b3);
    cudaStreamWaitEvent(s_aux, ev_sW2, 0);
    gemm_mma<<<dim3(8, 8, 2), 256, SMEM_BYTES, s_aux>>>(
        s16p, SCDIM, 0, s16p, SCDIM, 0, SCDIM,
        w2p, SCDIM, 0,  nullptr, 0,
        p2, HDIM, 0, (long)BROWS * HDIM, SCDIM, 2, 2);
    cudaEventRecord(ev_b2, s_aux);
    transpose_to_bf16<<<dim3(1024 / 64, 4096 / 64, GGRP), 256, 0, s_aux>>>(Wb1, wb1t, 4096, 1024);
    transpose_to_bf16<<<dim3(3072 / 64, 1024 / 64, GGRP), 256, 0, s_aux>>>(Wb2, wb2t, 1024, 3072);
    cudaEventRecord(ev_join, s_aux);

    // ---- main: rmsnorms (p1 from branch1; p2/p3 after aux ev_b2) ----
    rmsnorm_multi<1><<<BROWS, 256>>>(p1, (long)BROWS * HDIM, 4, b1, s1, x16, XDIM, 0);
    cudaStreamWaitEvent((cudaStream_t)0, ev_b2, 0);
    rmsnorm_multi<1><<<BROWS, 256>>>(p2, (long)BROWS * HDIM, 2, b2, s2, x16, XDIM, 1024);
    rmsnorm_multi<1><<<BROWS, 256>>>(p3, 0, 1, nullptr, s3, x16, XDIM, 2048);

    // ---- join: transposes must be done before grouped GEMMs ----
    cudaStreamWaitEvent((cudaStream_t)0, ev_join, 0);

    // Grouped GEMM 1 (split-K 2, partials): [x | d_g] @ Wb1t[g] -> g_ph
    gemm_mma<<<dim3(8, 8, GGRP * 2), 256, SMEM_BYTES>>>(
        x16, XDIM, 0,
        d16, DDIM, 1024, XDIM,
        wb1t, KB1, (long)HDIM * KB1,
        nullptr, 0,
        ph, DDIM, HDIM, (long)BROWS * DDIM, KB1, 2, 2);

    rmsnorm_multi<8><<<BROWS, 256>>>(ph, (long)BROWS * DDIM, 2, bb1, sb1, h16, DDIM, 0);

    // Grouped GEMM 2 (store + bias): h_g @ Wb2t[g] -> g_y
    gemm_mma<<<dim3(8, 24, GGRP), 256, SMEM_BYTES>>>(
        h16, DDIM, 1024,
        h16, DDIM, 1024, HDIM,
        wb2t, HDIM, (long)NB2 * HDIM,
        bb2, NB2,
        yp, YDIM, NB2, 0, HDIM, 1, 0);

    gate_kernel<<<(BROWS * DDIM) / 256, 256>>>(deter, out);
}